// round 9
// baseline (speedup 1.0000x reference)
#include <cuda_runtime.h>

// Fully fused UpFIRDn2d (crop -> bias -> up2 -> sep FIR12 -> leaky*sqrt2 -> sep FIR12 -> dn2)
// Polyphase up taps (pl=5 correlation):
//   y[2m]   = sum e[k]*x[m-3+k] (k=0..6), e = {f0, f1+f2, f3+f4, f5+f6, f7+f8, f9+f10, f11}
//   y[2m+1] = sum o[k]*x[m-2+k] (k=0..5), o = {f0+f1, f2+f3, f4+f5, f6+f7, f8+f9, f10+f11}
// Upsampled coords valid only on [0,256) per axis; outside -> 0 (dn-conv pad).
// S2/S3/S4 use packed fp32x2 FMA. S2 streams its window (k-outer) so live regs
// fit the 42-reg budget for 6 CTAs/SM.
//
// SMEM regions (floats), aliased by lifetime:
//   A [0,5624):     s_x (43 x p46) S0/S1;  a (74 x p76) S2/S3
//   B [5624,9120):  t1 (46 x p76, rows 43-45 garbage but guarded) S1/S2;
//                   t2 (74 x p36) S3/S4
// Total 9120 floats = 36.5 KB -> 6 CTAs = 219 KB <= 228 KB.

#define NTHR 256
#define PX 46
#define PT 76
#define P2 36
#define RB_OFF 5624
#define SM_TOTAL (5624 + 46 * PT)   // 9120 floats

typedef unsigned long long u64;

__device__ __forceinline__ u64 pk2(float lo, float hi) {
    u64 r; asm("mov.b64 %0, {%1, %2};" : "=l"(r) : "f"(lo), "f"(hi)); return r;
}
__device__ __forceinline__ void upk2(u64 v, float& lo, float& hi) {
    asm("mov.b64 {%0, %1}, %2;" : "=f"(lo), "=f"(hi) : "l"(v));
}
__device__ __forceinline__ u64 ffma2(u64 a, u64 b, u64 c) {
    u64 d; asm("fma.rn.f32x2 %0, %1, %2, %3;" : "=l"(d) : "l"(a), "l"(b), "l"(c)); return d;
}

__global__ __launch_bounds__(NTHR, 6)
void upfirdn2d_fused_kernel(const float* __restrict__ x,
                            const float* __restrict__ bias,
                            const float* __restrict__ fup,
                            const float* __restrict__ fdn,
                            float* __restrict__ out)
{
    __shared__ float smem[SM_TOTAL];
    float* s_x  = smem;              // pitch 46 (S0-S1)
    float* s_a  = smem;              // pitch 76 (S2-S3), aliases s_x
    float* s_t1 = smem + RB_OFF;     // pitch 76 (S1-S2)
    float* s_t2 = smem + RB_OFF;     // pitch 36 (S3-S4), aliases t1

    const int tid = threadIdx.x;
    const int bc  = blockIdx.y;
    const int Y0  = (blockIdx.x >> 2) * 32;
    const int X0  = (blockIdx.x & 3)  * 32;
    const bool x_int = (X0 != 0) && (X0 != 96);
    const bool y_int = (Y0 != 0) && (Y0 != 96);

    // polyphase up taps (scalar, live through S1 only)
    float e[7], o[6];
    {
        float up[12];
        #pragma unroll
        for (int k = 0; k < 12; k++) up[k] = fup[k];
        e[0] = up[0]; e[6] = up[11];
        #pragma unroll
        for (int j = 1; j < 6; j++) e[j] = up[2*j - 1] + up[2*j];
        #pragma unroll
        for (int j = 0; j < 6; j++) o[j] = up[2*j] + up[2*j + 1];
    }
    const float bv = bias[bc & 63];
    const float* xin = x + (size_t)bc * (130 * 130);

    // ---- S0: input tile + halo (43 x 44), bias, zero pad ----
    {
        const int lane = tid & 31, w = tid >> 5;
        if (x_int && y_int) {
            #pragma unroll
            for (int rr = 0; rr < 6; rr++) {
                int r = w + 8 * rr;
                if (r < 43) {
                    const float* src = xin + (Y0 - 4 + r) * 130 + (X0 - 5);
                    float* dst = s_x + r * PX;
                    #pragma unroll
                    for (int ci = 0; ci < 2; ci++) {
                        int cc = lane + 32 * ci;
                        if (cc < 44) dst[cc] = src[cc] + bv;
                    }
                }
            }
        } else {
            #pragma unroll
            for (int rr = 0; rr < 6; rr++) {
                int r = w + 8 * rr;
                if (r < 43) {
                    int gy = Y0 - 5 + r;
                    bool rowok = (unsigned)gy < 128u;
                    const float* src = xin + (gy + 1) * 130 + (X0 - 5);
                    float* dst = s_x + r * PX;
                    #pragma unroll
                    for (int ci = 0; ci < 2; ci++) {
                        int cc = lane + 32 * ci;
                        if (cc < 44) {
                            int gx = X0 - 6 + cc;
                            float v = 0.0f;
                            if (rowok && (unsigned)gx < 128u) v = src[cc] + bv;
                            dst[cc] = v;
                        }
                    }
                }
            }
        }
    }
    __syncthreads();

    // ---- S1: horizontal polyphase up -> t1[43][74] ----
    #pragma unroll
    for (int it = 0; it < 2; it++) {
        int u = tid + 256 * it;
        if (u < 43 * 9) {
            int r  = u / 9;
            int tp = u - r * 9;
            const float2* row2 = reinterpret_cast<const float2*>(s_x + r * PX + 4 * tp);
            float2 q0 = row2[0], q1 = row2[1], q2 = row2[2],
                   q3 = row2[3], q4 = row2[4], q5 = row2[5];
            float xw[12] = {q0.x,q0.y,q1.x,q1.y,q2.x,q2.y,
                            q3.x,q3.y,q4.x,q4.y,q5.x,q5.y};
            float res[8];
            #pragma unroll
            for (int p = 0; p < 4; p++) {
                float vo = o[0]*xw[p+1] + o[1]*xw[p+2] + o[2]*xw[p+3]
                         + o[3]*xw[p+4] + o[4]*xw[p+5] + o[5]*xw[p+6];
                float ve = e[0]*xw[p+1] + e[1]*xw[p+2] + e[2]*xw[p+3] + e[3]*xw[p+4]
                         + e[4]*xw[p+5] + e[5]*xw[p+6] + e[6]*xw[p+7];
                if (!x_int) {
                    int gc = 2 * X0 - 5 + 8 * tp + 2 * p;
                    vo = ((unsigned)gc       < 256u) ? vo : 0.f;
                    ve = ((unsigned)(gc + 1) < 256u) ? ve : 0.f;
                }
                res[2*p] = vo; res[2*p + 1] = ve;
            }
            float* dst = s_t1 + r * PT + 8 * tp;
            *reinterpret_cast<float4*>(dst)     = make_float4(res[0],res[1],res[2],res[3]);
            *reinterpret_cast<float4*>(dst + 4) = make_float4(res[4],res[5],res[6],res[7]);
            if (tp == 8) {   // pair 36 -> t1 cols 72,73; window xw[5..11]
                float vo = o[0]*xw[5] + o[1]*xw[6] + o[2]*xw[7]
                         + o[3]*xw[8] + o[4]*xw[9] + o[5]*xw[10];
                float ve = e[0]*xw[5] + e[1]*xw[6] + e[2]*xw[7] + e[3]*xw[8]
                         + e[4]*xw[9] + e[5]*xw[10] + e[6]*xw[11];
                if (!x_int) {
                    int gc = 2 * X0 - 5 + 72;
                    vo = ((unsigned)gc       < 256u) ? vo : 0.f;
                    ve = ((unsigned)(gc + 1) < 256u) ? ve : 0.f;
                }
                *reinterpret_cast<float2*>(dst + 8) = make_float2(vo, ve);
            }
        }
    }

    // pack up taps as (o[k], e[k]) with leaky gain sqrt(2) folded in
    // (sign test invariant under positive scale); scalars e/o dead after this.
    u64 poe[7];
    {
        const float G = 1.41421356237309515f;
        #pragma unroll
        for (int k = 0; k < 6; k++) poe[k] = pk2(o[k] * G, e[k] * G);
        poe[6] = pk2(0.0f, e[6] * G);
    }
    __syncthreads();

    // ---- S2: vertical polyphase up + leaky -> a[74][74]; packed, streamed ----
    // unit (g, ac2): col-pair, row-pairs i = 4g..4g+3 (i<37 guards garbage rows).
    // facX[p] = (vo, ve) for lane .x; stream window rows k=0..9:
    //   facX[p] += poe[k-p] * bcast(W[k].x)  when 0 <= k-p < 7.
    #pragma unroll
    for (int it = 0; it < 2; it++) {
        int u = tid + 256 * it;
        if (u < 10 * 37) {
            int g   = u / 37;
            int ac2 = u - g * 37;
            const float* base = s_t1 + (4 * g) * PT + 2 * ac2;
            u64 facx[4] = {0,0,0,0};
            u64 facy[4] = {0,0,0,0};
            #pragma unroll
            for (int k = 0; k < 10; k++) {
                float2 w = *reinterpret_cast<const float2*>(base + k * PT);
                u64 bx = pk2(w.x, w.x);
                u64 by = pk2(w.y, w.y);
                #pragma unroll
                for (int p = 0; p < 4; p++) {
                    const int kk = k - p;
                    if (kk >= 0 && kk < 7) {
                        facx[p] = ffma2(poe[kk], bx, facx[p]);
                        facy[p] = ffma2(poe[kk], by, facy[p]);
                    }
                }
            }
            float* adst = s_a + (8 * g) * PT + 2 * ac2;
            #pragma unroll
            for (int p = 0; p < 4; p++) {
                int i = 4 * g + p;
                if (i < 37) {
                    float vox, vex, voy, vey;
                    upk2(facx[p], vox, vex);
                    upk2(facy[p], voy, vey);
                    if (!y_int) {
                        int gr = 2 * Y0 - 5 + 2 * i;
                        bool ok0 = (unsigned)gr       < 256u;
                        bool ok1 = (unsigned)(gr + 1) < 256u;
                        vox = ok0 ? vox : 0.f;  voy = ok0 ? voy : 0.f;
                        vex = ok1 ? vex : 0.f;  vey = ok1 ? vey : 0.f;
                    }
                    float2 ro, re;
                    ro.x = (vox >= 0.f) ? vox : 0.2f * vox;
                    ro.y = (voy >= 0.f) ? voy : 0.2f * voy;
                    re.x = (vex >= 0.f) ? vex : 0.2f * vex;
                    re.y = (vey >= 0.f) ? vey : 0.2f * vey;
                    *reinterpret_cast<float2*>(adst + (2 * p)     * PT) = ro;
                    *reinterpret_cast<float2*>(adst + (2 * p + 1) * PT) = re;
                }
            }
        }
    }
    __syncthreads();

    // dn taps as packed pairs: pdn[m] = (dn[2m], dn[2m+1])
    u64 pdn[6];
    #pragma unroll
    for (int m = 0; m < 6; m++) pdn[m] = pk2(fdn[2*m], fdn[2*m + 1]);

    // ---- S3: horizontal dn-conv, stride-2 -> t2[74][32]; packed f32x2 ----
    #pragma unroll
    for (int it = 0; it < 2; it++) {
        int u = tid + 256 * it;
        if (u < 4 * 74) {
            int t  = u / 74;
            int ar = u - t * 74;
            const float4* row = reinterpret_cast<const float4*>(s_a + ar * PT + 16 * t);
            u64 facc[8] = {0,0,0,0,0,0,0,0};
            #pragma unroll
            for (int j = 0; j < 7; j++) {
                float4 qv = row[j];
                u64 pelA = pk2(qv.x, qv.y);
                u64 pelB = pk2(qv.z, qv.w);
                const int nA = 2 * j, nB = 2 * j + 1;
                #pragma unroll
                for (int q = 0; q < 8; q++) {
                    int mA = nA - q;
                    if (mA >= 0 && mA < 6) facc[q] = ffma2(pdn[mA], pelA, facc[q]);
                    int mB = nB - q;
                    if (mB >= 0 && mB < 6) facc[q] = ffma2(pdn[mB], pelB, facc[q]);
                }
            }
            float acc[8];
            #pragma unroll
            for (int q = 0; q < 8; q++) {
                float lo, hi; upk2(facc[q], lo, hi);
                acc[q] = lo + hi;
            }
            float* dst = s_t2 + ar * P2 + 8 * t;
            *reinterpret_cast<float4*>(dst)     = make_float4(acc[0],acc[1],acc[2],acc[3]);
            *reinterpret_cast<float4*>(dst + 4) = make_float4(acc[4],acc[5],acc[6],acc[7]);
        }
    }
    __syncthreads();

    // ---- S4: vertical dn-conv, stride-2 -> out; packed f32x2 over col pairs ----
    if (tid < 128) {
        int cp = tid & 15;
        int yg = tid >> 4;
        float dns[12];
        #pragma unroll
        for (int m = 0; m < 6; m++) upk2(pdn[m], dns[2*m], dns[2*m + 1]);
        const float* base = s_t2 + (8 * yg) * P2 + 2 * cp;
        u64 R2[18];
        #pragma unroll
        for (int k = 0; k < 18; k++)
            R2[k] = *reinterpret_cast<const u64*>(base + k * P2);
        u64 facc[4] = {0,0,0,0};
        #pragma unroll
        for (int k = 0; k < 12; k++) {
            u64 d2 = pk2(dns[k], dns[k]);
            #pragma unroll
            for (int q = 0; q < 4; q++)
                facc[q] = ffma2(d2, R2[k + 2*q], facc[q]);
        }
        float* op = out + ((size_t)bc * 128 + (Y0 + 4 * yg)) * 128 + X0 + 2 * cp;
        #pragma unroll
        for (int q = 0; q < 4; q++)
            *reinterpret_cast<u64*>(op + q * 128) = facc[q];
    }
}

extern "C" void kernel_launch(void* const* d_in, const int* in_sizes, int n_in,
                              void* d_out, int out_size)
{
    const float* x    = (const float*)d_in[0];   // (8,64,130,130) fp32
    const float* bias = (const float*)d_in[1];   // (64,) fp32
    const float* fup  = (const float*)d_in[2];   // (12,) fp32
    const float* fdn  = (const float*)d_in[3];   // (12,) fp32
    float* out = (float*)d_out;                  // (8,64,128,128) fp32

    dim3 grid(16, 512);
    upfirdn2d_fused_kernel<<<grid, NTHR>>>(x, bias, fup, fdn, out);
}

// round 10
// speedup vs baseline: 1.0488x; 1.0488x over previous
#include <cuda_runtime.h>

// Fully fused UpFIRDn2d (crop -> bias -> up2 -> sep FIR12 -> leaky*sqrt2 -> sep FIR12 -> dn2)
// Polyphase up taps (pl=5 correlation):
//   y[2m]   = sum e[k]*x[m-3+k] (k=0..6), e = {f0, f1+f2, f3+f4, f5+f6, f7+f8, f9+f10, f11}
//   y[2m+1] = sum o[k]*x[m-2+k] (k=0..5), o = {f0+f1, f2+f3, f4+f5, f6+f7, f8+f9, f10+f11}
// Upsampled coords valid only on [0,256) per axis; outside -> 0 (dn-conv pad).
// S3/S4 packed fp32x2 FMA; S2 scalar with split-batch window (register peak <= 42
// for 6 CTAs/SM).
//
// SMEM regions (floats), aliased by lifetime:
//   A [0,5624):     s_x (43 x p46) S0/S1;  a (74 x p76) S2/S3
//   B [5624,9120):  t1 (46 x p76, rows 43-45 garbage but guarded) S1/S2;
//                   t2 (74 x p36) S3/S4
// Total 9120 floats = 36.5 KB -> 6 CTAs = 219 KB <= 228 KB.

#define NTHR 256
#define PX 46
#define PT 76
#define P2 36
#define RB_OFF 5624
#define SM_TOTAL (5624 + 46 * PT)   // 9120 floats

typedef unsigned long long u64;

__device__ __forceinline__ u64 pk2(float lo, float hi) {
    u64 r; asm("mov.b64 %0, {%1, %2};" : "=l"(r) : "f"(lo), "f"(hi)); return r;
}
__device__ __forceinline__ void upk2(u64 v, float& lo, float& hi) {
    asm("mov.b64 {%0, %1}, %2;" : "=f"(lo), "=f"(hi) : "l"(v));
}
__device__ __forceinline__ u64 ffma2(u64 a, u64 b, u64 c) {
    u64 d; asm("fma.rn.f32x2 %0, %1, %2, %3;" : "=l"(d) : "l"(a), "l"(b), "l"(c)); return d;
}

__global__ __launch_bounds__(NTHR, 6)
void upfirdn2d_fused_kernel(const float* __restrict__ x,
                            const float* __restrict__ bias,
                            const float* __restrict__ fup,
                            const float* __restrict__ fdn,
                            float* __restrict__ out)
{
    __shared__ float smem[SM_TOTAL];
    float* s_x  = smem;              // pitch 46 (S0-S1)
    float* s_a  = smem;              // pitch 76 (S2-S3), aliases s_x
    float* s_t1 = smem + RB_OFF;     // pitch 76 (S1-S2)
    float* s_t2 = smem + RB_OFF;     // pitch 36 (S3-S4), aliases t1

    const int tid = threadIdx.x;
    const int bc  = blockIdx.y;
    const int Y0  = (blockIdx.x >> 2) * 32;
    const int X0  = (blockIdx.x & 3)  * 32;
    const bool x_int = (X0 != 0) && (X0 != 96);
    const bool y_int = (Y0 != 0) && (Y0 != 96);

    // polyphase up taps
    float e[7], o[6];
    {
        float up[12];
        #pragma unroll
        for (int k = 0; k < 12; k++) up[k] = fup[k];
        e[0] = up[0]; e[6] = up[11];
        #pragma unroll
        for (int j = 1; j < 6; j++) e[j] = up[2*j - 1] + up[2*j];
        #pragma unroll
        for (int j = 0; j < 6; j++) o[j] = up[2*j] + up[2*j + 1];
    }
    const float bv = bias[bc & 63];
    const float* xin = x + (size_t)bc * (130 * 130);

    // ---- S0: input tile + halo (43 x 44), bias, zero pad ----
    {
        const int lane = tid & 31, w = tid >> 5;
        if (x_int && y_int) {
            #pragma unroll
            for (int rr = 0; rr < 6; rr++) {
                int r = w + 8 * rr;
                if (r < 43) {
                    const float* src = xin + (Y0 - 4 + r) * 130 + (X0 - 5);
                    float* dst = s_x + r * PX;
                    #pragma unroll
                    for (int ci = 0; ci < 2; ci++) {
                        int cc = lane + 32 * ci;
                        if (cc < 44) dst[cc] = src[cc] + bv;
                    }
                }
            }
        } else {
            #pragma unroll
            for (int rr = 0; rr < 6; rr++) {
                int r = w + 8 * rr;
                if (r < 43) {
                    int gy = Y0 - 5 + r;
                    bool rowok = (unsigned)gy < 128u;
                    const float* src = xin + (gy + 1) * 130 + (X0 - 5);
                    float* dst = s_x + r * PX;
                    #pragma unroll
                    for (int ci = 0; ci < 2; ci++) {
                        int cc = lane + 32 * ci;
                        if (cc < 44) {
                            int gx = X0 - 6 + cc;
                            float v = 0.0f;
                            if (rowok && (unsigned)gx < 128u) v = src[cc] + bv;
                            dst[cc] = v;
                        }
                    }
                }
            }
        }
    }
    __syncthreads();

    // ---- S1: horizontal polyphase up -> t1[43][74] ----
    #pragma unroll
    for (int it = 0; it < 2; it++) {
        int u = tid + 256 * it;
        if (u < 43 * 9) {
            int r  = u / 9;
            int tp = u - r * 9;
            const float2* row2 = reinterpret_cast<const float2*>(s_x + r * PX + 4 * tp);
            float2 q0 = row2[0], q1 = row2[1], q2 = row2[2],
                   q3 = row2[3], q4 = row2[4], q5 = row2[5];
            float xw[12] = {q0.x,q0.y,q1.x,q1.y,q2.x,q2.y,
                            q3.x,q3.y,q4.x,q4.y,q5.x,q5.y};
            float res[8];
            #pragma unroll
            for (int p = 0; p < 4; p++) {
                float vo = o[0]*xw[p+1] + o[1]*xw[p+2] + o[2]*xw[p+3]
                         + o[3]*xw[p+4] + o[4]*xw[p+5] + o[5]*xw[p+6];
                float ve = e[0]*xw[p+1] + e[1]*xw[p+2] + e[2]*xw[p+3] + e[3]*xw[p+4]
                         + e[4]*xw[p+5] + e[5]*xw[p+6] + e[6]*xw[p+7];
                if (!x_int) {
                    int gc = 2 * X0 - 5 + 8 * tp + 2 * p;
                    vo = ((unsigned)gc       < 256u) ? vo : 0.f;
                    ve = ((unsigned)(gc + 1) < 256u) ? ve : 0.f;
                }
                res[2*p] = vo; res[2*p + 1] = ve;
            }
            float* dst = s_t1 + r * PT + 8 * tp;
            *reinterpret_cast<float4*>(dst)     = make_float4(res[0],res[1],res[2],res[3]);
            *reinterpret_cast<float4*>(dst + 4) = make_float4(res[4],res[5],res[6],res[7]);
            if (tp == 8) {   // pair 36 -> t1 cols 72,73; window xw[5..11]
                float vo = o[0]*xw[5] + o[1]*xw[6] + o[2]*xw[7]
                         + o[3]*xw[8] + o[4]*xw[9] + o[5]*xw[10];
                float ve = e[0]*xw[5] + e[1]*xw[6] + e[2]*xw[7] + e[3]*xw[8]
                         + e[4]*xw[9] + e[5]*xw[10] + e[6]*xw[11];
                if (!x_int) {
                    int gc = 2 * X0 - 5 + 72;
                    vo = ((unsigned)gc       < 256u) ? vo : 0.f;
                    ve = ((unsigned)(gc + 1) < 256u) ? ve : 0.f;
                }
                *reinterpret_cast<float2*>(dst + 8) = make_float2(vo, ve);
            }
        }
    }

    // fold leaky gain sqrt(2) into up taps (sign test invariant under positive scale)
    {
        const float G = 1.41421356237309515f;
        #pragma unroll
        for (int k = 0; k < 7; k++) e[k] *= G;
        #pragma unroll
        for (int k = 0; k < 6; k++) o[k] *= G;
    }
    __syncthreads();

    // ---- S2: vertical polyphase up + leaky -> a[74][74]; scalar, split-batch ----
    // unit (g, ac2): col-pair (2ac2, 2ac2+1), row-pairs i = 4g..4g+3 (i<37 guards
    // garbage t1 rows). Window rows 0..9 loaded in two batches of 5 (reg peak low).
    // Row kk contributes: o[kk-p] to pair p's vo (0<=kk-p<6), e[kk-p] to ve (<7).
    #pragma unroll
    for (int it = 0; it < 2; it++) {
        int u = tid + 256 * it;
        if (u < 10 * 37) {
            int g   = u / 37;
            int ac2 = u - g * 37;
            const float* base = s_t1 + (4 * g) * PT + 2 * ac2;
            float vox[4] = {0,0,0,0}, voy[4] = {0,0,0,0};
            float vex[4] = {0,0,0,0}, vey[4] = {0,0,0,0};
            #pragma unroll
            for (int kb = 0; kb < 2; kb++) {
                float2 W[5];
                #pragma unroll
                for (int k = 0; k < 5; k++)
                    W[k] = *reinterpret_cast<const float2*>(base + (5*kb + k) * PT);
                #pragma unroll
                for (int k = 0; k < 5; k++) {
                    const int kk = 5*kb + k;
                    #pragma unroll
                    for (int p = 0; p < 4; p++) {
                        const int d = kk - p;
                        if (d >= 0 && d < 6) {
                            vox[p] += o[d] * W[k].x;
                            voy[p] += o[d] * W[k].y;
                        }
                        if (d >= 0 && d < 7) {
                            vex[p] += e[d] * W[k].x;
                            vey[p] += e[d] * W[k].y;
                        }
                    }
                }
            }
            float* adst = s_a + (8 * g) * PT + 2 * ac2;
            #pragma unroll
            for (int p = 0; p < 4; p++) {
                int i = 4 * g + p;
                if (i < 37) {
                    float ox = vox[p], oy = voy[p], ex = vex[p], ey = vey[p];
                    if (!y_int) {
                        int gr = 2 * Y0 - 5 + 2 * i;
                        bool ok0 = (unsigned)gr       < 256u;
                        bool ok1 = (unsigned)(gr + 1) < 256u;
                        ox = ok0 ? ox : 0.f;  oy = ok0 ? oy : 0.f;
                        ex = ok1 ? ex : 0.f;  ey = ok1 ? ey : 0.f;
                    }
                    float2 ro, re;
                    ro.x = (ox >= 0.f) ? ox : 0.2f * ox;
                    ro.y = (oy >= 0.f) ? oy : 0.2f * oy;
                    re.x = (ex >= 0.f) ? ex : 0.2f * ex;
                    re.y = (ey >= 0.f) ? ey : 0.2f * ey;
                    *reinterpret_cast<float2*>(adst + (2 * p)     * PT) = ro;
                    *reinterpret_cast<float2*>(adst + (2 * p + 1) * PT) = re;
                }
            }
        }
    }
    __syncthreads();

    // dn taps as packed pairs: pdn[m] = (dn[2m], dn[2m+1])
    u64 pdn[6];
    #pragma unroll
    for (int m = 0; m < 6; m++) pdn[m] = pk2(fdn[2*m], fdn[2*m + 1]);

    // ---- S3: horizontal dn-conv, stride-2 -> t2[74][32]; packed f32x2 ----
    #pragma unroll
    for (int it = 0; it < 2; it++) {
        int u = tid + 256 * it;
        if (u < 4 * 74) {
            int t  = u / 74;
            int ar = u - t * 74;
            const float4* row = reinterpret_cast<const float4*>(s_a + ar * PT + 16 * t);
            u64 facc[8] = {0,0,0,0,0,0,0,0};
            #pragma unroll
            for (int j = 0; j < 7; j++) {
                float4 qv = row[j];
                u64 pelA = pk2(qv.x, qv.y);
                u64 pelB = pk2(qv.z, qv.w);
                const int nA = 2 * j, nB = 2 * j + 1;
                #pragma unroll
                for (int q = 0; q < 8; q++) {
                    int mA = nA - q;
                    if (mA >= 0 && mA < 6) facc[q] = ffma2(pdn[mA], pelA, facc[q]);
                    int mB = nB - q;
                    if (mB >= 0 && mB < 6) facc[q] = ffma2(pdn[mB], pelB, facc[q]);
                }
            }
            float acc[8];
            #pragma unroll
            for (int q = 0; q < 8; q++) {
                float lo, hi; upk2(facc[q], lo, hi);
                acc[q] = lo + hi;
            }
            float* dst = s_t2 + ar * P2 + 8 * t;
            *reinterpret_cast<float4*>(dst)     = make_float4(acc[0],acc[1],acc[2],acc[3]);
            *reinterpret_cast<float4*>(dst + 4) = make_float4(acc[4],acc[5],acc[6],acc[7]);
        }
    }
    __syncthreads();

    // ---- S4: vertical dn-conv, stride-2 -> out; packed f32x2, streamed loads ----
    // thread: 4 rows x 2 cols; broadcast taps hoisted (d2[12]), R2 streamed.
    if (tid < 128) {
        int cp = tid & 15;
        int yg = tid >> 4;
        u64 d2[12];
        #pragma unroll
        for (int m = 0; m < 6; m++) {
            float a_, b_; upk2(pdn[m], a_, b_);
            d2[2*m]     = pk2(a_, a_);
            d2[2*m + 1] = pk2(b_, b_);
        }
        const float* base = s_t2 + (8 * yg) * P2 + 2 * cp;
        u64 facc[4] = {0,0,0,0};
        #pragma unroll
        for (int j = 0; j < 18; j++) {
            u64 r = *reinterpret_cast<const u64*>(base + j * P2);
            #pragma unroll
            for (int q = 0; q < 4; q++) {
                const int k = j - 2 * q;
                if (k >= 0 && k < 12) facc[q] = ffma2(d2[k], r, facc[q]);
            }
        }
        float* op = out + ((size_t)bc * 128 + (Y0 + 4 * yg)) * 128 + X0 + 2 * cp;
        #pragma unroll
        for (int q = 0; q < 4; q++)
            *reinterpret_cast<u64*>(op + q * 128) = facc[q];
    }
}

extern "C" void kernel_launch(void* const* d_in, const int* in_sizes, int n_in,
                              void* d_out, int out_size)
{
    const float* x    = (const float*)d_in[0];   // (8,64,130,130) fp32
    const float* bias = (const float*)d_in[1];   // (64,) fp32
    const float* fup  = (const float*)d_in[2];   // (12,) fp32
    const float* fdn  = (const float*)d_in[3];   // (12,) fp32
    float* out = (float*)d_out;                  // (8,64,128,128) fp32

    dim3 grid(16, 512);
    upfirdn2d_fused_kernel<<<grid, NTHR>>>(x, bias, fup, fdn, out);
}